// round 5
// baseline (speedup 1.0000x reference)
#include <cuda_runtime.h>
#include <math.h>

// ---------------- problem constants ----------------
#define FQ     2049
#define NT     1500
#define TLEN   1535976
#define NFFT   4096
#define HOP    1024
#define NSRC   4
#define NCHUNK 5
#define WINLEN 300
#define EPSV   1e-10f
#define SQEPS  1e-5f

// ---------------- device scratch ----------------
__device__ float2 g_mix[2 * FQ * NT];          // [c][f][t]
__device__ float  g_mag[2 * FQ * NT];          // [c][f][t]
__device__ float  g_V[8 * FQ * NT];            // [s*2+c][f][t]
__device__ float2 g_Y[8 * FQ * NT];            // [s*2+c][f][t]
__device__ float  g_frames[8 * NT * NFFT];
__device__ float2 g_tw[3072];                  // e^{-2pi i j/4096}, j<3072 (radix-4 needs 3k)
__device__ float  g_win[NFFT];
__device__ int    g_cmax[NCHUNK];

// ---------------- helpers ----------------
__device__ __forceinline__ float2 cmul(float2 a, float2 b) {
    return make_float2(a.x * b.x - a.y * b.y, a.x * b.y + a.y * b.x);
}
__device__ __forceinline__ float2 cadd(float2 a, float2 b) {
    return make_float2(a.x + b.x, a.y + b.y);
}
// base-4 digit reversal of 12-bit index
__device__ __forceinline__ int rev4(int n) {
    unsigned r = __brev((unsigned)n) >> 20;
    return (int)(((r & 0x555u) << 1) | ((r >> 1) & 0x555u));
}
__device__ __forceinline__ unsigned f2tf(float f) {
    unsigned r;
    asm("cvt.rna.tf32.f32 %0, %1;" : "=r"(r) : "f"(f));
    return r;
}

// in-place radix-4 DIT FFT4096, input pre-loaded in base-4-digit-reversed order.
// sign=-1 forward, +1 inverse (unscaled). 6 stages.
__device__ void fft4096_r4(float2* sh, int sign) {
#pragma unroll
    for (int st = 0; st < 6; st++) {
        const int q = 1 << (2 * st);
        const int stepT = 1024 >> (2 * st);
        for (int j = threadIdx.x; j < 1024; j += 256) {
            int k = j & (q - 1);
            int base = ((j - k) << 2) + k;
            float2 w1 = g_tw[k * stepT];
            float2 w2 = g_tw[2 * k * stepT];
            float2 w3 = g_tw[3 * k * stepT];
            if (sign > 0) { w1.y = -w1.y; w2.y = -w2.y; w3.y = -w3.y; }
            float2 a0 = sh[base];
            float2 a1 = cmul(sh[base + q], w1);
            float2 a2 = cmul(sh[base + 2 * q], w2);
            float2 a3 = cmul(sh[base + 3 * q], w3);
            float2 b0 = make_float2(a0.x + a2.x, a0.y + a2.y);
            float2 b1 = make_float2(a0.x - a2.x, a0.y - a2.y);
            float2 b2 = make_float2(a1.x + a3.x, a1.y + a3.y);
            float2 b3 = make_float2(a1.x - a3.x, a1.y - a3.y);
            float2 rot = (sign < 0) ? make_float2(b3.y, -b3.x)   // -j*b3
                                    : make_float2(-b3.y, b3.x);  // +j*b3
            sh[base]         = make_float2(b0.x + b2.x, b0.y + b2.y);
            sh[base + q]     = make_float2(b1.x + rot.x, b1.y + rot.y);
            sh[base + 2 * q] = make_float2(b0.x - b2.x, b0.y - b2.y);
            sh[base + 3 * q] = make_float2(b1.x - rot.x, b1.y - rot.y);
        }
        __syncthreads();
    }
}

// ---------------- init ----------------
__global__ void init_kernel() {
    int i = blockIdx.x * blockDim.x + threadIdx.x;
    if (i < 3072) {
        float s, c;
        sincospif(i * (1.0f / 2048.0f), &s, &c);
        g_tw[i] = make_float2(c, -s);
    }
    if (i < NFFT) {
        g_win[i] = 0.5f * (1.0f - cospif(i * (1.0f / 2048.0f)));
    }
    if (i < NCHUNK) g_cmax[i] = 0;
}

// ---------------- STFT: both channels packed in one complex FFT ----------------
__global__ __launch_bounds__(256) void stft_kernel(const float* __restrict__ audio) {
    __shared__ float2 sh[NFFT];
    __shared__ float smax[256];
    int t = blockIdx.x;
    for (int n = threadIdx.x; n < NFFT; n += 256) {
        int j = t * HOP + n - (NFFT / 2);
        if (j < 0) j = -j;
        if (j >= TLEN) j = 2 * (TLEN - 1) - j;
        float w = g_win[n];
        sh[rev4(n)] = make_float2(audio[j] * w, audio[TLEN + j] * w);
    }
    __syncthreads();
    fft4096_r4(sh, -1);
    float lmax = 0.f;
    for (int f = threadIdx.x; f <= NFFT / 2; f += 256) {
        float2 A = sh[f];
        float2 Zn = sh[(NFFT - f) & (NFFT - 1)];
        // X0 = 0.5(A + conj(Zn));  X1 = 0.5(A.y+Zn.y, Zn.x-A.x)
        float2 x0 = make_float2(0.5f * (A.x + Zn.x), 0.5f * (A.y - Zn.y));
        float2 x1 = make_float2(0.5f * (A.y + Zn.y), 0.5f * (Zn.x - A.x));
        int i0 = (0 * FQ + f) * NT + t;
        int i1 = (1 * FQ + f) * NT + t;
        g_mix[i0] = x0;
        g_mix[i1] = x1;
        float m0 = sqrtf(x0.x * x0.x + x0.y * x0.y);
        float m1 = sqrtf(x1.x * x1.x + x1.y * x1.y);
        g_mag[i0] = m0;
        g_mag[i1] = m1;
        lmax = fmaxf(lmax, fmaxf(m0, m1));
    }
    smax[threadIdx.x] = lmax;
    __syncthreads();
    for (int off = 128; off; off >>= 1) {
        if (threadIdx.x < off) smax[threadIdx.x] = fmaxf(smax[threadIdx.x], smax[threadIdx.x + off]);
        __syncthreads();
    }
    if (threadIdx.x == 0) atomicMax(&g_cmax[t / WINLEN], __float_as_int(smax[0]));
}

// ---------------- V = relu(W[s] @ mag[c]) : pipelined 3xTF32 MMA ----------------
// Block tile 128x128x16, double-buffered fp32 smem, hi/lo split at fragment load.
__global__ __launch_bounds__(256) void gemm_tc_kernel(const float* __restrict__ Wmat) {
    const int sc = blockIdx.z;
    const float* A = Wmat + (sc >> 1) * FQ * FQ;   // [m][k]
    const float* B = g_mag + (sc & 1) * FQ * NT;   // [k][n]
    float* C = g_V + sc * FQ * NT;                 // [m][n]

    __shared__ float As[2][16][136];   // [buf][k][m]
    __shared__ float Bs[2][16][136];   // [buf][k][n]

    const int tid = threadIdx.x;
    const int lane = tid & 31, warp = tid >> 5;
    const int wm = (warp >> 2) * 64;
    const int wn = (warp & 3) * 32;
    const int row0 = blockIdx.y * 128, col0 = blockIdx.x * 128;

    const int a_row = tid >> 1;          // 0..127
    const int a_k = (tid & 1) * 8;       // 0 or 8
    const int b_col = lane * 4;          // 0..124
    const int b_row = warp;              // 0..7

    const int grow = row0 + a_row;
    const bool gvalid = grow < FQ;
    const int fr = lane >> 2, kc = lane & 3;

    float acc[4][4][4];
#pragma unroll
    for (int i = 0; i < 4; i++)
#pragma unroll
        for (int j = 0; j < 4; j++)
#pragma unroll
            for (int q = 0; q < 4; q++) acc[i][j][q] = 0.f;

    float pa[8];
    float4 pb[2];

    // tile loaders: gmem -> regs
    auto load_regs = [&](int k0) {
#pragma unroll
        for (int i = 0; i < 8; i++) {
            int k = k0 + a_k + i;
            pa[i] = (gvalid && k < FQ) ? __ldg(&A[grow * FQ + k]) : 0.f;
        }
#pragma unroll
        for (int r = 0; r < 2; r++) {
            int k = k0 + b_row + r * 8;
            int col = col0 + b_col;
            float4 v = make_float4(0.f, 0.f, 0.f, 0.f);
            if (k < FQ) {
                if (col + 3 < NT) {
                    v = *(const float4*)&B[k * NT + col];
                } else {
                    if (col < NT)     v.x = B[k * NT + col];
                    if (col + 1 < NT) v.y = B[k * NT + col + 1];
                    if (col + 2 < NT) v.z = B[k * NT + col + 2];
                }
            }
            pb[r] = v;
        }
    };
    auto store_smem = [&](int buf) {
#pragma unroll
        for (int i = 0; i < 8; i++) As[buf][a_k + i][a_row] = pa[i];
#pragma unroll
        for (int r = 0; r < 2; r++) {
            int kk = b_row + r * 8;
            Bs[buf][kk][b_col]     = pb[r].x;
            Bs[buf][kk][b_col + 1] = pb[r].y;
            Bs[buf][kk][b_col + 2] = pb[r].z;
            Bs[buf][kk][b_col + 3] = pb[r].w;
        }
    };

    load_regs(0);
    store_smem(0);
    __syncthreads();

    int buf = 0;
    for (int k0 = 0; k0 < FQ; k0 += 16) {
        const bool has_next = (k0 + 16 < FQ);
        if (has_next) load_regs(k0 + 16);

#pragma unroll
        for (int ks = 0; ks < 16; ks += 8) {
            unsigned ah[4][4], al[4][4];
#pragma unroll
            for (int i = 0; i < 4; i++) {
                int m = wm + i * 16;
#pragma unroll
                for (int q = 0; q < 4; q++) {
                    float v = As[buf][ks + kc + (q >> 1) * 4][m + fr + (q & 1) * 8];
                    unsigned hb = f2tf(v);
                    ah[i][q] = hb;
                    al[i][q] = f2tf(v - __uint_as_float(hb));
                }
            }
#pragma unroll
            for (int j = 0; j < 4; j++) {
                int n = wn + j * 8;
                float v0 = Bs[buf][ks + kc][n + fr];
                float v1 = Bs[buf][ks + kc + 4][n + fr];
                unsigned bh0 = f2tf(v0), bh1 = f2tf(v1);
                unsigned bl0 = f2tf(v0 - __uint_as_float(bh0));
                unsigned bl1 = f2tf(v1 - __uint_as_float(bh1));
#pragma unroll
                for (int i = 0; i < 4; i++) {
                    asm volatile(
                        "mma.sync.aligned.m16n8k8.row.col.f32.tf32.tf32.f32 "
                        "{%0,%1,%2,%3}, {%4,%5,%6,%7}, {%8,%9}, {%0,%1,%2,%3};\n"
                        : "+f"(acc[i][j][0]), "+f"(acc[i][j][1]),
                          "+f"(acc[i][j][2]), "+f"(acc[i][j][3])
                        : "r"(ah[i][0]), "r"(ah[i][1]), "r"(ah[i][2]), "r"(ah[i][3]),
                          "r"(bl0), "r"(bl1));
                    asm volatile(
                        "mma.sync.aligned.m16n8k8.row.col.f32.tf32.tf32.f32 "
                        "{%0,%1,%2,%3}, {%4,%5,%6,%7}, {%8,%9}, {%0,%1,%2,%3};\n"
                        : "+f"(acc[i][j][0]), "+f"(acc[i][j][1]),
                          "+f"(acc[i][j][2]), "+f"(acc[i][j][3])
                        : "r"(al[i][0]), "r"(al[i][1]), "r"(al[i][2]), "r"(al[i][3]),
                          "r"(bh0), "r"(bh1));
                    asm volatile(
                        "mma.sync.aligned.m16n8k8.row.col.f32.tf32.tf32.f32 "
                        "{%0,%1,%2,%3}, {%4,%5,%6,%7}, {%8,%9}, {%0,%1,%2,%3};\n"
                        : "+f"(acc[i][j][0]), "+f"(acc[i][j][1]),
                          "+f"(acc[i][j][2]), "+f"(acc[i][j][3])
                        : "r"(ah[i][0]), "r"(ah[i][1]), "r"(ah[i][2]), "r"(ah[i][3]),
                          "r"(bh0), "r"(bh1));
                }
            }
        }
        if (has_next) {
            store_smem(buf ^ 1);
            __syncthreads();
            buf ^= 1;
        }
    }

    // epilogue: relu + store (float2 per pair of adjacent cols)
    const int cc = (lane & 3) * 2;
#pragma unroll
    for (int i = 0; i < 4; i++) {
        int row = row0 + wm + i * 16 + fr;
#pragma unroll
        for (int j = 0; j < 4; j++) {
            int col = col0 + wn + j * 8 + cc;
            if (row < FQ && col + 1 < NT) {
                *(float2*)&C[row * NT + col] =
                    make_float2(fmaxf(acc[i][j][0], 0.f), fmaxf(acc[i][j][1], 0.f));
            } else if (row < FQ && col < NT) {
                C[row * NT + col] = fmaxf(acc[i][j][0], 0.f);
            }
            if (row + 8 < FQ && col + 1 < NT) {
                *(float2*)&C[(row + 8) * NT + col] =
                    make_float2(fmaxf(acc[i][j][2], 0.f), fmaxf(acc[i][j][3], 0.f));
            } else if (row + 8 < FQ && col < NT) {
                C[(row + 8) * NT + col] = fmaxf(acc[i][j][2], 0.f);
            }
        }
    }
}

// ---------------- Wiener EM ----------------
__global__ __launch_bounds__(128) void wiener_kernel() {
    const int f = blockIdx.x, ck = blockIdx.y;
    const int tid = threadIdx.x;
    const float ma = fmaxf(1.0f, __int_as_float(g_cmax[ck]) * 0.1f);
    const float ima = 1.0f / ma;

    float r00[NSRC], r11[NSRC], r01r[NSRC], r01i[NSRC], vs[NSRC];
#pragma unroll
    for (int s = 0; s < NSRC; s++) { r00[s] = r11[s] = r01r[s] = r01i[s] = vs[s] = 0.f; }

    for (int t = tid; t < WINLEN; t += 128) {
        int tg = ck * WINLEN + t;
        float2 x0 = g_mix[(0 * FQ + f) * NT + tg];
        float2 x1 = g_mix[(1 * FQ + f) * NT + tg];
        float a0 = sqrtf(x0.x * x0.x + x0.y * x0.y);
        float a1 = sqrtf(x1.x * x1.x + x1.y * x1.y);
        float2 p0 = (a0 > 0.f) ? make_float2(x0.x / a0, x0.y / a0) : make_float2(1.f, 0.f);
        float2 p1 = (a1 > 0.f) ? make_float2(x1.x / a1, x1.y / a1) : make_float2(1.f, 0.f);
        float2 pc = make_float2(p0.x * p1.x + p0.y * p1.y, p0.y * p1.x - p0.x * p1.y);
#pragma unroll
        for (int s = 0; s < NSRC; s++) {
            float v0 = g_V[((s * 2 + 0) * FQ + f) * NT + tg] * ima;
            float v1 = g_V[((s * 2 + 1) * FQ + f) * NT + tg] * ima;
            r00[s] += v0 * v0;
            r11[s] += v1 * v1;
            float cr = v0 * v1;
            r01r[s] += cr * pc.x;
            r01i[s] += cr * pc.y;
            vs[s] += 0.5f * (v0 * v0 + v1 * v1);
        }
    }

    __shared__ float sacc[20][128];
#pragma unroll
    for (int s = 0; s < NSRC; s++) {
        sacc[s][tid] = r00[s];
        sacc[4 + s][tid] = r11[s];
        sacc[8 + s][tid] = r01r[s];
        sacc[12 + s][tid] = r01i[s];
        sacc[16 + s][tid] = vs[s];
    }
    __syncthreads();
    for (int off = 64; off; off >>= 1) {
        if (tid < off) {
#pragma unroll
            for (int q = 0; q < 20; q++) sacc[q][tid] += sacc[q][tid + off];
        }
        __syncthreads();
    }
    __shared__ float sR[16];
    if (tid < NSRC) {
        int s = tid;
        float inv = 1.0f / (EPSV + sacc[16 + s][0]);
        sR[s * 4 + 0] = sacc[s][0] * inv;
        sR[s * 4 + 1] = sacc[4 + s][0] * inv;
        sR[s * 4 + 2] = sacc[8 + s][0] * inv;
        sR[s * 4 + 3] = sacc[12 + s][0] * inv;
    }
    __syncthreads();

    float R00[NSRC], R11[NSRC], R01x[NSRC], R01y[NSRC];
#pragma unroll
    for (int s = 0; s < NSRC; s++) {
        R00[s] = sR[s * 4 + 0];
        R11[s] = sR[s * 4 + 1];
        R01x[s] = sR[s * 4 + 2];
        R01y[s] = sR[s * 4 + 3];
    }

    for (int t = tid; t < WINLEN; t += 128) {
        int tg = ck * WINLEN + t;
        float2 x0 = g_mix[(0 * FQ + f) * NT + tg];
        float2 x1 = g_mix[(1 * FQ + f) * NT + tg];
        float2 xs0 = make_float2(x0.x * ima, x0.y * ima);
        float2 xs1 = make_float2(x1.x * ima, x1.y * ima);

        float vloc[NSRC];
        float c00 = SQEPS, c11 = SQEPS, c01r = 0.f, c01i = 0.f;
#pragma unroll
        for (int s = 0; s < NSRC; s++) {
            float v0 = g_V[((s * 2 + 0) * FQ + f) * NT + tg] * ima;
            float v1 = g_V[((s * 2 + 1) * FQ + f) * NT + tg] * ima;
            float v = 0.5f * (v0 * v0 + v1 * v1);
            vloc[s] = v;
            c00 += v * R00[s];
            c11 += v * R11[s];
            c01r += v * R01x[s];
            c01i += v * R01y[s];
        }
        float det = c00 * c11 - (c01r * c01r + c01i * c01i);
        float idet = 1.0f / det;
        float i00 = c11 * idet, i11 = c00 * idet;
        float2 i01 = make_float2(-c01r * idet, -c01i * idet);
        float2 i10 = make_float2(-c01r * idet, c01i * idet);

#pragma unroll
        for (int s = 0; s < NSRC; s++) {
            float v = vloc[s];
            float a00 = R00[s], a11 = R11[s];
            float2 a01 = make_float2(R01x[s], R01y[s]);
            float2 a10 = make_float2(R01x[s], -R01y[s]);
            float2 G00 = make_float2(a00 * i00 + a01.x * i10.x - a01.y * i10.y,
                                     a01.x * i10.y + a01.y * i10.x);
            float2 G01 = make_float2(a00 * i01.x + a01.x * i11,
                                     a00 * i01.y + a01.y * i11);
            float2 G10 = make_float2(a10.x * i00 + a11 * i10.x,
                                     a10.y * i00 + a11 * i10.y);
            float2 G11 = make_float2(a10.x * i01.x - a10.y * i01.y + a11 * i11,
                                     a10.x * i01.y + a10.y * i01.x);
            G00.x *= v; G00.y *= v; G01.x *= v; G01.y *= v;
            G10.x *= v; G10.y *= v; G11.x *= v; G11.y *= v;

            float2 y0 = cadd(cmul(G00, xs0), cmul(G01, xs1));
            float2 y1 = cadd(cmul(G10, xs0), cmul(G11, xs1));
            g_Y[((s * 2 + 0) * FQ + f) * NT + tg] = make_float2(y0.x * ma, y0.y * ma);
            g_Y[((s * 2 + 1) * FQ + f) * NT + tg] = make_float2(y1.x * ma, y1.y * ma);
        }
    }
}

// ---------------- ISTFT: channel pair (2 real outputs) per complex inverse FFT ----------------
__global__ __launch_bounds__(256) void istft_kernel() {
    __shared__ float2 sh[NFFT];
    int t = blockIdx.x, s = blockIdx.y;
    for (int f = threadIdx.x; f <= NFFT / 2; f += 256) {
        float2 y0 = g_Y[((s * 2 + 0) * FQ + f) * NT + t];
        float2 y1 = g_Y[((s * 2 + 1) * FQ + f) * NT + t];
        // Z[f] = Y0 + i*Y1 ; Z[N-f] = conj(Y0) + i*conj(Y1)
        sh[rev4(f)] = make_float2(y0.x - y1.y, y0.y + y1.x);
        if (f > 0 && f < NFFT / 2)
            sh[rev4(NFFT - f)] = make_float2(y0.x + y1.y, y1.x - y0.y);
    }
    __syncthreads();
    fft4096_r4(sh, +1);
    float* out0 = g_frames + ((s * 2 + 0) * NT + t) * NFFT;
    float* out1 = g_frames + ((s * 2 + 1) * NT + t) * NFFT;
    const float scale = 1.0f / NFFT;
    for (int n = threadIdx.x; n < NFFT; n += 256) {
        float2 z = sh[n];
        float ws = scale * g_win[n];
        out0[n] = z.x * ws;
        out1[n] = z.y * ws;
    }
}

// ---------------- overlap-add gather ----------------
__global__ __launch_bounds__(256) void gather_kernel(float* __restrict__ out) {
    int idx = blockIdx.x * blockDim.x + threadIdx.x;
    if (idx >= 8 * TLEN) return;
    int sc = idx / TLEN;
    int io = idx - sc * TLEN;
    int i = io + NFFT / 2;
    int tmin = (i - 3072) / 1024;
    if (tmin < 0) tmin = 0;
    int tmax = i / HOP;
    if (tmax > NT - 1) tmax = NT - 1;
    float num = 0.f, den = 0.f;
    for (int tt = tmin; tt <= tmax; ++tt) {
        int n = i - tt * HOP;
        num += g_frames[(sc * NT + tt) * NFFT + n];
        float wv = g_win[n];
        den += wv * wv;
    }
    out[idx] = num / ((den > 1e-11f) ? den : 1.0f);
}

// ---------------- launch ----------------
extern "C" void kernel_launch(void* const* d_in, const int* in_sizes, int n_in,
                              void* d_out, int out_size) {
    const float* audio = (const float*)d_in[0];
    const float* Wmat = (const float*)d_in[1];
    float* out = (float*)d_out;

    init_kernel<<<16, 256>>>();
    stft_kernel<<<NT, 256>>>(audio);
    gemm_tc_kernel<<<dim3((NT + 127) / 128, (FQ + 127) / 128, 8), 256>>>(Wmat);
    wiener_kernel<<<dim3(FQ, NCHUNK), 128>>>();
    istft_kernel<<<dim3(NT, NSRC), 256>>>();
    gather_kernel<<<(8 * TLEN + 255) / 256, 256>>>(out);
}

// round 9
// speedup vs baseline: 2.2527x; 2.2527x over previous
#include <cuda_runtime.h>
#include <cuda_bf16.h>
#include <math.h>

#define FQ     2049
#define NT     1500
#define TLEN   1535976
#define NFFT   4096
#define HOP    1024
#define NSRC   4
#define NCHUNK 5
#define WINLEN 300
#define EPSV   1e-10f
#define SQEPS  1e-5f

__device__ float2 g_mix[2 * FQ * NT];
__device__ float  g_mag[2 * FQ * NT];
__device__ float  g_V[8 * FQ * NT];
__device__ float2 g_Y[8 * FQ * NT];
__device__ float  g_frames[8 * NT * NFFT];
__device__ float2 g_tw[3072];
__device__ float  g_win[NFFT];
__device__ int    g_cmax[NCHUNK];

__device__ __forceinline__ float2 cmul(float2 a, float2 b) {
    return make_float2(a.x * b.x - a.y * b.y, a.x * b.y + a.y * b.x);
}
__device__ __forceinline__ float2 cadd(float2 a, float2 b) {
    return make_float2(a.x + b.x, a.y + b.y);
}
__device__ __forceinline__ int rev4(int n) {
    unsigned r = __brev((unsigned)n) >> 20;
    return (int)(((r & 0x555u) << 1) | ((r >> 1) & 0x555u));
}
// pack [bf16(v) | bf16(v - bf16(v))] into one word
__device__ __forceinline__ unsigned packsplit(float v) {
    __nv_bfloat16 h = __float2bfloat16(v);
    float hf = __bfloat162float(h);
    __nv_bfloat16 m = __float2bfloat16(v - hf);
    return ((unsigned)__bfloat16_as_ushort(h) << 16) | (unsigned)__bfloat16_as_ushort(m);
}

__device__ void fft4096_r4(float2* sh, int sign) {
#pragma unroll
    for (int st = 0; st < 6; st++) {
        const int q = 1 << (2 * st);
        const int stepT = 1024 >> (2 * st);
        for (int j = threadIdx.x; j < 1024; j += 256) {
            int k = j & (q - 1);
            int base = ((j - k) << 2) + k;
            float2 w1 = g_tw[k * stepT];
            float2 w2 = g_tw[2 * k * stepT];
            float2 w3 = g_tw[3 * k * stepT];
            if (sign > 0) { w1.y = -w1.y; w2.y = -w2.y; w3.y = -w3.y; }
            float2 a0 = sh[base];
            float2 a1 = cmul(sh[base + q], w1);
            float2 a2 = cmul(sh[base + 2 * q], w2);
            float2 a3 = cmul(sh[base + 3 * q], w3);
            float2 b0 = make_float2(a0.x + a2.x, a0.y + a2.y);
            float2 b1 = make_float2(a0.x - a2.x, a0.y - a2.y);
            float2 b2 = make_float2(a1.x + a3.x, a1.y + a3.y);
            float2 b3 = make_float2(a1.x - a3.x, a1.y - a3.y);
            float2 rot = (sign < 0) ? make_float2(b3.y, -b3.x)
                                    : make_float2(-b3.y, b3.x);
            sh[base]         = make_float2(b0.x + b2.x, b0.y + b2.y);
            sh[base + q]     = make_float2(b1.x + rot.x, b1.y + rot.y);
            sh[base + 2 * q] = make_float2(b0.x - b2.x, b0.y - b2.y);
            sh[base + 3 * q] = make_float2(b1.x - rot.x, b1.y - rot.y);
        }
        __syncthreads();
    }
}

__global__ void init_kernel() {
    int i = blockIdx.x * blockDim.x + threadIdx.x;
    if (i < 3072) {
        float s, c;
        sincospif(i * (1.0f / 2048.0f), &s, &c);
        g_tw[i] = make_float2(c, -s);
    }
    if (i < NFFT) g_win[i] = 0.5f * (1.0f - cospif(i * (1.0f / 2048.0f)));
    if (i < NCHUNK) g_cmax[i] = 0;
}

__global__ __launch_bounds__(256) void stft_kernel(const float* __restrict__ audio) {
    __shared__ float2 sh[NFFT];
    __shared__ float smax[256];
    int t = blockIdx.x;
    for (int n = threadIdx.x; n < NFFT; n += 256) {
        int j = t * HOP + n - (NFFT / 2);
        if (j < 0) j = -j;
        if (j >= TLEN) j = 2 * (TLEN - 1) - j;
        float w = g_win[n];
        sh[rev4(n)] = make_float2(audio[j] * w, audio[TLEN + j] * w);
    }
    __syncthreads();
    fft4096_r4(sh, -1);
    float lmax = 0.f;
    for (int f = threadIdx.x; f <= NFFT / 2; f += 256) {
        float2 A = sh[f];
        float2 Zn = sh[(NFFT - f) & (NFFT - 1)];
        float2 x0 = make_float2(0.5f * (A.x + Zn.x), 0.5f * (A.y - Zn.y));
        float2 x1 = make_float2(0.5f * (A.y + Zn.y), 0.5f * (Zn.x - A.x));
        int i0 = (0 * FQ + f) * NT + t;
        int i1 = (1 * FQ + f) * NT + t;
        g_mix[i0] = x0;
        g_mix[i1] = x1;
        float m0 = sqrtf(x0.x * x0.x + x0.y * x0.y);
        float m1 = sqrtf(x1.x * x1.x + x1.y * x1.y);
        g_mag[i0] = m0;
        g_mag[i1] = m1;
        lmax = fmaxf(lmax, fmaxf(m0, m1));
    }
    smax[threadIdx.x] = lmax;
    __syncthreads();
    for (int off = 128; off; off >>= 1) {
        if (threadIdx.x < off) smax[threadIdx.x] = fmaxf(smax[threadIdx.x], smax[threadIdx.x + off]);
        __syncthreads();
    }
    if (threadIdx.x == 0) atomicMax(&g_cmax[t / WINLEN], __float_as_int(smax[0]));
}

// ---------------- V = relu(W @ mag) : bf16x3 split on m16n8k16 MMA ----------------
#define MMA_BF16(d, a0, a1, a2, a3, b0, b1)                                      \
    asm volatile("mma.sync.aligned.m16n8k16.row.col.f32.bf16.bf16.f32 "          \
                 "{%0,%1,%2,%3}, {%4,%5,%6,%7}, {%8,%9}, {%0,%1,%2,%3};\n"       \
                 : "+f"(d[0]), "+f"(d[1]), "+f"(d[2]), "+f"(d[3])                 \
                 : "r"(a0), "r"(a1), "r"(a2), "r"(a3), "r"(b0), "r"(b1))

__global__ __launch_bounds__(256) void gemm_tc_kernel(const float* __restrict__ Wmat) {
    const int sc = blockIdx.z;
    const float* A = Wmat + (sc >> 1) * FQ * FQ;   // [m][k]
    const float* B = g_mag + (sc & 1) * FQ * NT;   // [k][n]
    float* C = g_V + sc * FQ * NT;                 // [m][n]

    __shared__ __align__(16) unsigned As[2][16][132];  // packed [hi|mid]
    __shared__ __align__(16) unsigned Bs[2][16][132];

    const int tid = threadIdx.x;
    const int lane = tid & 31, warp = tid >> 5;
    const int wm = (warp >> 2) * 64;
    const int wn = (warp & 3) * 32;
    const int row0 = blockIdx.y * 128, col0 = blockIdx.x * 128;

    const int a_row = tid >> 1;
    const int a_k = (tid & 1) * 8;
    const int b_col = lane * 4;
    const int b_row = warp;

    const int grow = row0 + a_row;
    const bool gvalid = grow < FQ;
    const int fr = lane >> 2, kc = lane & 3;

    float acc[4][4][4];
#pragma unroll
    for (int i = 0; i < 4; i++)
#pragma unroll
        for (int j = 0; j < 4; j++)
#pragma unroll
            for (int q = 0; q < 4; q++) acc[i][j][q] = 0.f;

    float pa[8];
    float4 pb[2];

    auto load_regs = [&](int k0) {
#pragma unroll
        for (int i = 0; i < 8; i++) {
            int k = k0 + a_k + i;
            pa[i] = (gvalid && k < FQ) ? __ldg(&A[grow * FQ + k]) : 0.f;
        }
#pragma unroll
        for (int r = 0; r < 2; r++) {
            int k = k0 + b_row + r * 8;
            int col = col0 + b_col;
            float4 v = make_float4(0.f, 0.f, 0.f, 0.f);
            if (k < FQ) {
                if (col + 3 < NT) {
                    v = *(const float4*)&B[k * NT + col];
                } else {
                    if (col < NT)     v.x = B[k * NT + col];
                    if (col + 1 < NT) v.y = B[k * NT + col + 1];
                    if (col + 2 < NT) v.z = B[k * NT + col + 2];
                }
            }
            pb[r] = v;
        }
    };
    auto store_smem = [&](int buf) {
#pragma unroll
        for (int i = 0; i < 8; i++) As[buf][a_k + i][a_row] = packsplit(pa[i]);
#pragma unroll
        for (int r = 0; r < 2; r++) {
            uint4 w;
            w.x = packsplit(pb[r].x);
            w.y = packsplit(pb[r].y);
            w.z = packsplit(pb[r].z);
            w.w = packsplit(pb[r].w);
            *(uint4*)&Bs[buf][b_row + r * 8][b_col] = w;
        }
    };

    load_regs(0);
    store_smem(0);
    __syncthreads();

    const int k0a = 2 * kc, k0b = 2 * kc + 1;  // fragment k indices (lo pair); +8 for hi pair
    int buf = 0;
    for (int k0 = 0; k0 < FQ; k0 += 16) {
        const bool has_next = (k0 + 16 < FQ);
        if (has_next) load_regs(k0 + 16);

        // A fragments: hi and mid via byte_perm of packed words
        unsigned ah[4][4], al[4][4];
#pragma unroll
        for (int i = 0; i < 4; i++) {
            int m = wm + i * 16 + fr;
            unsigned w00 = As[buf][k0a][m],     w01 = As[buf][k0b][m];
            unsigned w10 = As[buf][k0a][m + 8], w11 = As[buf][k0b][m + 8];
            unsigned w02 = As[buf][k0a + 8][m],     w03 = As[buf][k0b + 8][m];
            unsigned w12 = As[buf][k0a + 8][m + 8], w13 = As[buf][k0b + 8][m + 8];
            ah[i][0] = __byte_perm(w00, w01, 0x7632); al[i][0] = __byte_perm(w00, w01, 0x5410);
            ah[i][1] = __byte_perm(w10, w11, 0x7632); al[i][1] = __byte_perm(w10, w11, 0x5410);
            ah[i][2] = __byte_perm(w02, w03, 0x7632); al[i][2] = __byte_perm(w02, w03, 0x5410);
            ah[i][3] = __byte_perm(w12, w13, 0x7632); al[i][3] = __byte_perm(w12, w13, 0x5410);
        }
#pragma unroll
        for (int j = 0; j < 4; j++) {
            int n = wn + j * 8 + fr;
            unsigned u0 = Bs[buf][k0a][n],     u1 = Bs[buf][k0b][n];
            unsigned u2 = Bs[buf][k0a + 8][n], u3 = Bs[buf][k0b + 8][n];
            unsigned bh0 = __byte_perm(u0, u1, 0x7632), bl0 = __byte_perm(u0, u1, 0x5410);
            unsigned bh1 = __byte_perm(u2, u3, 0x7632), bl1 = __byte_perm(u2, u3, 0x5410);
#pragma unroll
            for (int i = 0; i < 4; i++) {
                MMA_BF16(acc[i][j], ah[i][0], ah[i][1], ah[i][2], ah[i][3], bl0, bl1);
                MMA_BF16(acc[i][j], al[i][0], al[i][1], al[i][2], al[i][3], bh0, bh1);
                MMA_BF16(acc[i][j], ah[i][0], ah[i][1], ah[i][2], ah[i][3], bh0, bh1);
            }
        }
        if (has_next) {
            store_smem(buf ^ 1);
            __syncthreads();
            buf ^= 1;
        }
    }

    const int cc = (lane & 3) * 2;
#pragma unroll
    for (int i = 0; i < 4; i++) {
        int row = row0 + wm + i * 16 + fr;
#pragma unroll
        for (int j = 0; j < 4; j++) {
            int col = col0 + wn + j * 8 + cc;
            if (row < FQ && col + 1 < NT) {
                *(float2*)&C[row * NT + col] =
                    make_float2(fmaxf(acc[i][j][0], 0.f), fmaxf(acc[i][j][1], 0.f));
            } else if (row < FQ && col < NT) {
                C[row * NT + col] = fmaxf(acc[i][j][0], 0.f);
            }
            if (row + 8 < FQ && col + 1 < NT) {
                *(float2*)&C[(row + 8) * NT + col] =
                    make_float2(fmaxf(acc[i][j][2], 0.f), fmaxf(acc[i][j][3], 0.f));
            } else if (row + 8 < FQ && col < NT) {
                C[(row + 8) * NT + col] = fmaxf(acc[i][j][2], 0.f);
            }
        }
    }
}

__global__ __launch_bounds__(128) void wiener_kernel() {
    const int f = blockIdx.x, ck = blockIdx.y;
    const int tid = threadIdx.x;
    const float ma = fmaxf(1.0f, __int_as_float(g_cmax[ck]) * 0.1f);
    const float ima = 1.0f / ma;

    float r00[NSRC], r11[NSRC], r01r[NSRC], r01i[NSRC], vs[NSRC];
#pragma unroll
    for (int s = 0; s < NSRC; s++) { r00[s] = r11[s] = r01r[s] = r01i[s] = vs[s] = 0.f; }

    for (int t = tid; t < WINLEN; t += 128) {
        int tg = ck * WINLEN + t;
        float2 x0 = g_mix[(0 * FQ + f) * NT + tg];
        float2 x1 = g_mix[(1 * FQ + f) * NT + tg];
        float a0 = sqrtf(x0.x * x0.x + x0.y * x0.y);
        float a1 = sqrtf(x1.x * x1.x + x1.y * x1.y);
        float2 p0 = (a0 > 0.f) ? make_float2(x0.x / a0, x0.y / a0) : make_float2(1.f, 0.f);
        float2 p1 = (a1 > 0.f) ? make_float2(x1.x / a1, x1.y / a1) : make_float2(1.f, 0.f);
        float2 pc = make_float2(p0.x * p1.x + p0.y * p1.y, p0.y * p1.x - p0.x * p1.y);
#pragma unroll
        for (int s = 0; s < NSRC; s++) {
            float v0 = g_V[((s * 2 + 0) * FQ + f) * NT + tg] * ima;
            float v1 = g_V[((s * 2 + 1) * FQ + f) * NT + tg] * ima;
            r00[s] += v0 * v0;
            r11[s] += v1 * v1;
            float cr = v0 * v1;
            r01r[s] += cr * pc.x;
            r01i[s] += cr * pc.y;
            vs[s] += 0.5f * (v0 * v0 + v1 * v1);
        }
    }

    __shared__ float sacc[20][128];
#pragma unroll
    for (int s = 0; s < NSRC; s++) {
        sacc[s][tid] = r00[s];
        sacc[4 + s][tid] = r11[s];
        sacc[8 + s][tid] = r01r[s];
        sacc[12 + s][tid] = r01i[s];
        sacc[16 + s][tid] = vs[s];
    }
    __syncthreads();
    for (int off = 64; off; off >>= 1) {
        if (tid < off) {
#pragma unroll
            for (int q = 0; q < 20; q++) sacc[q][tid] += sacc[q][tid + off];
        }
        __syncthreads();
    }
    __shared__ float sR[16];
    if (tid < NSRC) {
        int s = tid;
        float inv = 1.0f / (EPSV + sacc[16 + s][0]);
        sR[s * 4 + 0] = sacc[s][0] * inv;
        sR[s * 4 + 1] = sacc[4 + s][0] * inv;
        sR[s * 4 + 2] = sacc[8 + s][0] * inv;
        sR[s * 4 + 3] = sacc[12 + s][0] * inv;
    }
    __syncthreads();

    float R00[NSRC], R11[NSRC], R01x[NSRC], R01y[NSRC];
#pragma unroll
    for (int s = 0; s < NSRC; s++) {
        R00[s] = sR[s * 4 + 0];
        R11[s] = sR[s * 4 + 1];
        R01x[s] = sR[s * 4 + 2];
        R01y[s] = sR[s * 4 + 3];
    }

    for (int t = tid; t < WINLEN; t += 128) {
        int tg = ck * WINLEN + t;
        float2 x0 = g_mix[(0 * FQ + f) * NT + tg];
        float2 x1 = g_mix[(1 * FQ + f) * NT + tg];
        float2 xs0 = make_float2(x0.x * ima, x0.y * ima);
        float2 xs1 = make_float2(x1.x * ima, x1.y * ima);

        float vloc[NSRC];
        float c00 = SQEPS, c11 = SQEPS, c01r = 0.f, c01i = 0.f;
#pragma unroll
        for (int s = 0; s < NSRC; s++) {
            float v0 = g_V[((s * 2 + 0) * FQ + f) * NT + tg] * ima;
            float v1 = g_V[((s * 2 + 1) * FQ + f) * NT + tg] * ima;
            float v = 0.5f * (v0 * v0 + v1 * v1);
            vloc[s] = v;
            c00 += v * R00[s];
            c11 += v * R11[s];
            c01r += v * R01x[s];
            c01i += v * R01y[s];
        }
        float det = c00 * c11 - (c01r * c01r + c01i * c01i);
        float idet = 1.0f / det;
        float i00 = c11 * idet, i11 = c00 * idet;
        float2 i01 = make_float2(-c01r * idet, -c01i * idet);
        float2 i10 = make_float2(-c01r * idet, c01i * idet);

#pragma unroll
        for (int s = 0; s < NSRC; s++) {
            float v = vloc[s];
            float a00 = R00[s], a11 = R11[s];
            float2 a01 = make_float2(R01x[s], R01y[s]);
            float2 a10 = make_float2(R01x[s], -R01y[s]);
            float2 G00 = make_float2(a00 * i00 + a01.x * i10.x - a01.y * i10.y,
                                     a01.x * i10.y + a01.y * i10.x);
            float2 G01 = make_float2(a00 * i01.x + a01.x * i11,
                                     a00 * i01.y + a01.y * i11);
            float2 G10 = make_float2(a10.x * i00 + a11 * i10.x,
                                     a10.y * i00 + a11 * i10.y);
            float2 G11 = make_float2(a10.x * i01.x - a10.y * i01.y + a11 * i11,
                                     a10.x * i01.y + a10.y * i01.x);
            G00.x *= v; G00.y *= v; G01.x *= v; G01.y *= v;
            G10.x *= v; G10.y *= v; G11.x *= v; G11.y *= v;

            float2 y0 = cadd(cmul(G00, xs0), cmul(G01, xs1));
            float2 y1 = cadd(cmul(G10, xs0), cmul(G11, xs1));
            g_Y[((s * 2 + 0) * FQ + f) * NT + tg] = make_float2(y0.x * ma, y0.y * ma);
            g_Y[((s * 2 + 1) * FQ + f) * NT + tg] = make_float2(y1.x * ma, y1.y * ma);
        }
    }
}

__global__ __launch_bounds__(256) void istft_kernel() {
    __shared__ float2 sh[NFFT];
    int t = blockIdx.x, s = blockIdx.y;
    for (int f = threadIdx.x; f <= NFFT / 2; f += 256) {
        float2 y0 = g_Y[((s * 2 + 0) * FQ + f) * NT + t];
        float2 y1 = g_Y[((s * 2 + 1) * FQ + f) * NT + t];
        sh[rev4(f)] = make_float2(y0.x - y1.y, y0.y + y1.x);
        if (f > 0 && f < NFFT / 2)
            sh[rev4(NFFT - f)] = make_float2(y0.x + y1.y, y1.x - y0.y);
    }
    __syncthreads();
    fft4096_r4(sh, +1);
    float* out0 = g_frames + ((s * 2 + 0) * NT + t) * NFFT;
    float* out1 = g_frames + ((s * 2 + 1) * NT + t) * NFFT;
    const float scale = 1.0f / NFFT;
    for (int n = threadIdx.x; n < NFFT; n += 256) {
        float2 z = sh[n];
        float ws = scale * g_win[n];
        out0[n] = z.x * ws;
        out1[n] = z.y * ws;
    }
}

__global__ __launch_bounds__(256) void gather_kernel(float* __restrict__ out) {
    int idx = blockIdx.x * blockDim.x + threadIdx.x;
    if (idx >= 8 * TLEN) return;
    int sc = idx / TLEN;
    int io = idx - sc * TLEN;
    int i = io + NFFT / 2;
    int tmin = (i - 3072) / 1024;
    if (tmin < 0) tmin = 0;
    int tmax = i / HOP;
    if (tmax > NT - 1) tmax = NT - 1;
    float num = 0.f, den = 0.f;
    for (int tt = tmin; tt <= tmax; ++tt) {
        int n = i - tt * HOP;
        num += g_frames[(sc * NT + tt) * NFFT + n];
        float wv = g_win[n];
        den += wv * wv;
    }
    out[idx] = num / ((den > 1e-11f) ? den : 1.0f);
}

extern "C" void kernel_launch(void* const* d_in, const int* in_sizes, int n_in,
                              void* d_out, int out_size) {
    const float* audio = (const float*)d_in[0];
    const float* Wmat = (const float*)d_in[1];
    float* out = (float*)d_out;

    init_kernel<<<16, 256>>>();
    stft_kernel<<<NT, 256>>>(audio);
    gemm_tc_kernel<<<dim3((NT + 127) / 128, (FQ + 127) / 128, 8), 256>>>(Wmat);
    wiener_kernel<<<dim3(FQ, NCHUNK), 128>>>();
    istft_kernel<<<dim3(NT, NSRC), 256>>>();
    gather_kernel<<<(8 * TLEN + 255) / 256, 256>>>(out);
}

// round 12
// speedup vs baseline: 2.8374x; 1.2595x over previous
#include <cuda_runtime.h>
#include <cuda_bf16.h>
#include <math.h>

#define FQ     2049
#define NT     1500
#define TLEN   1535976
#define NFFT   4096
#define HOP    1024
#define NSRC   4
#define NCHUNK 5
#define WINLEN 300
#define EPSV   1e-10f
#define SQEPS  1e-5f
#define KT     129        // k tiles of 16
#define GP     2176       // padded m (17*128)
#define TP     1536       // padded t (12*128)
#define FP2    2064       // padded f for magT

__device__ float2 g_mix[2 * FQ * NT];
__device__ float  g_V[8 * FQ * NT];
__device__ float2 g_Y[8 * FQ * NT];
__device__ float  g_frames[8 * NT * NFFT];
__device__ float2 g_tw[3072];
__device__ float  g_win[NFFT];
__device__ int    g_cmax[NCHUNK];
__device__ float  g_magT[2L * TP * FP2];                    // [c][t][f]
__device__ __align__(16) unsigned g_Ah[4L * KT * 8 * GP];   // packed [hi(k1)|hi(k0)]
__device__ __align__(16) unsigned g_Am[4L * KT * 8 * GP];
__device__ __align__(16) unsigned g_Bh[2L * KT * 8 * TP];
__device__ __align__(16) unsigned g_Bm[2L * KT * 8 * TP];

__device__ __forceinline__ float2 cmul(float2 a, float2 b) {
    return make_float2(a.x * b.x - a.y * b.y, a.x * b.y + a.y * b.x);
}
__device__ __forceinline__ float2 cadd(float2 a, float2 b) {
    return make_float2(a.x + b.x, a.y + b.y);
}
__device__ __forceinline__ int rev4(int n) {
    unsigned r = __brev((unsigned)n) >> 20;
    return (int)(((r & 0x555u) << 1) | ((r >> 1) & 0x555u));
}
__device__ __forceinline__ unsigned pack2(float v0, float v1, bool mid) {
    __nv_bfloat16 h0 = __float2bfloat16(v0), h1 = __float2bfloat16(v1);
    if (mid) {
        h0 = __float2bfloat16(v0 - __bfloat162float(h0));
        h1 = __float2bfloat16(v1 - __bfloat162float(h1));
    }
    return ((unsigned)__bfloat16_as_ushort(h1) << 16) | __bfloat16_as_ushort(h0);
}

__device__ void fft4096_r4(float2* sh, int sign) {
#pragma unroll
    for (int st = 0; st < 6; st++) {
        const int q = 1 << (2 * st);
        const int stepT = 1024 >> (2 * st);
        for (int j = threadIdx.x; j < 1024; j += 256) {
            int k = j & (q - 1);
            int base = ((j - k) << 2) + k;
            float2 w1 = g_tw[k * stepT];
            float2 w2 = g_tw[2 * k * stepT];
            float2 w3 = g_tw[3 * k * stepT];
            if (sign > 0) { w1.y = -w1.y; w2.y = -w2.y; w3.y = -w3.y; }
            float2 a0 = sh[base];
            float2 a1 = cmul(sh[base + q], w1);
            float2 a2 = cmul(sh[base + 2 * q], w2);
            float2 a3 = cmul(sh[base + 3 * q], w3);
            float2 b0 = make_float2(a0.x + a2.x, a0.y + a2.y);
            float2 b1 = make_float2(a0.x - a2.x, a0.y - a2.y);
            float2 b2 = make_float2(a1.x + a3.x, a1.y + a3.y);
            float2 b3 = make_float2(a1.x - a3.x, a1.y - a3.y);
            float2 rot = (sign < 0) ? make_float2(b3.y, -b3.x)
                                    : make_float2(-b3.y, b3.x);
            sh[base]         = make_float2(b0.x + b2.x, b0.y + b2.y);
            sh[base + q]     = make_float2(b1.x + rot.x, b1.y + rot.y);
            sh[base + 2 * q] = make_float2(b0.x - b2.x, b0.y - b2.y);
            sh[base + 3 * q] = make_float2(b1.x - rot.x, b1.y - rot.y);
        }
        __syncthreads();
    }
}

__global__ void init_kernel() {
    int i = blockIdx.x * blockDim.x + threadIdx.x;
    if (i < 3072) {
        float s, c;
        sincospif(i * (1.0f / 2048.0f), &s, &c);
        g_tw[i] = make_float2(c, -s);
    }
    if (i < NFFT) g_win[i] = 0.5f * (1.0f - cospif(i * (1.0f / 2048.0f)));
    if (i < NCHUNK) g_cmax[i] = 0;
}

// W[s][m][k] -> fragment-ready tiles [s][kt][p][m]
__global__ void packA_kernel(const float* __restrict__ W) {
    int kt = blockIdx.x, s = blockIdx.z;
    int m = blockIdx.y * 128 + threadIdx.x;
    long base = (((long)s * KT + kt) * 8) * GP + m;
    if (m >= FQ) {
#pragma unroll
        for (int p = 0; p < 8; p++) { g_Ah[base + p * GP] = 0; g_Am[base + p * GP] = 0; }
        return;
    }
    const float* Wr = W + (long)s * FQ * FQ + (long)m * FQ;
#pragma unroll
    for (int p = 0; p < 8; p++) {
        int k = kt * 16 + 2 * p;
        float v0 = (k < FQ) ? __ldg(&Wr[k]) : 0.f;
        float v1 = (k + 1 < FQ) ? __ldg(&Wr[k + 1]) : 0.f;
        g_Ah[base + p * GP] = pack2(v0, v1, false);
        g_Am[base + p * GP] = pack2(v0, v1, true);
    }
}

// magT[c][t][f] -> fragment-ready tiles [c][kt][p][t]
__global__ void packB_kernel() {
    int kt = blockIdx.x, c = blockIdx.z;
    int t = blockIdx.y * 128 + threadIdx.x;
    const float* Mr = g_magT + ((long)c * TP + t) * FP2 + kt * 16;
    long base = (((long)c * KT + kt) * 8) * TP + t;
#pragma unroll
    for (int p = 0; p < 8; p++) {
        float v0 = Mr[2 * p], v1 = Mr[2 * p + 1];
        g_Bh[base + p * TP] = pack2(v0, v1, false);
        g_Bm[base + p * TP] = pack2(v0, v1, true);
    }
}

__global__ __launch_bounds__(256) void stft_kernel(const float* __restrict__ audio) {
    __shared__ float2 sh[NFFT];
    __shared__ float smax[256];
    int t = blockIdx.x;
    for (int n = threadIdx.x; n < NFFT; n += 256) {
        int j = t * HOP + n - (NFFT / 2);
        if (j < 0) j = -j;
        if (j >= TLEN) j = 2 * (TLEN - 1) - j;
        float w = g_win[n];
        sh[rev4(n)] = make_float2(audio[j] * w, audio[TLEN + j] * w);
    }
    __syncthreads();
    fft4096_r4(sh, -1);
    float lmax = 0.f;
    for (int f = threadIdx.x; f <= NFFT / 2; f += 256) {
        float2 A = sh[f];
        float2 Zn = sh[(NFFT - f) & (NFFT - 1)];
        float2 x0 = make_float2(0.5f * (A.x + Zn.x), 0.5f * (A.y - Zn.y));
        float2 x1 = make_float2(0.5f * (A.y + Zn.y), 0.5f * (Zn.x - A.x));
        g_mix[(0 * FQ + f) * NT + t] = x0;
        g_mix[(1 * FQ + f) * NT + t] = x1;
        float m0 = sqrtf(x0.x * x0.x + x0.y * x0.y);
        float m1 = sqrtf(x1.x * x1.x + x1.y * x1.y);
        g_magT[(0L * TP + t) * FP2 + f] = m0;
        g_magT[(1L * TP + t) * FP2 + f] = m1;
        lmax = fmaxf(lmax, fmaxf(m0, m1));
    }
    smax[threadIdx.x] = lmax;
    __syncthreads();
    for (int off = 128; off; off >>= 1) {
        if (threadIdx.x < off) smax[threadIdx.x] = fmaxf(smax[threadIdx.x], smax[threadIdx.x + off]);
        __syncthreads();
    }
    if (threadIdx.x == 0) atomicMax(&g_cmax[t / WINLEN], __float_as_int(smax[0]));
}

// ---------------- GEMM: bf16x3, cp.async 3-stage, fragment-ready smem ----------------
#define AW   1088          // 8 rows * 136 words
#define STW  4352          // stage words (Ah,Am,Bh,Bm)
#define GSM  52224         // 3 * STW * 4

#define MMA_BF16(d, a0, a1, a2, a3, b0, b1)                                      \
    asm volatile("mma.sync.aligned.m16n8k16.row.col.f32.bf16.bf16.f32 "          \
                 "{%0,%1,%2,%3}, {%4,%5,%6,%7}, {%8,%9}, {%0,%1,%2,%3};\n"       \
                 : "+f"(d[0]), "+f"(d[1]), "+f"(d[2]), "+f"(d[3])                 \
                 : "r"(a0), "r"(a1), "r"(a2), "r"(a3), "r"(b0), "r"(b1))
#define CP16(d, s) asm volatile("cp.async.cg.shared.global [%0], [%1], 16;" :: "r"(d), "l"(s) : "memory")
#define CPCOMMIT() asm volatile("cp.async.commit_group;" ::: "memory")
#define CPWAIT1()  asm volatile("cp.async.wait_group 1;" ::: "memory")

__global__ __launch_bounds__(256, 2) void gemm_kernel() {
    extern __shared__ __align__(16) unsigned smw[];
    unsigned sb;
    asm("{ .reg .u64 t; cvta.to.shared.u64 t, %1; cvt.u32.u64 %0, t; }" : "=r"(sb) : "l"(smw));
    const int tid = threadIdx.x, warp = tid >> 5, lane = tid & 31;
    const int sc = blockIdx.z, s = sc >> 1, cch = sc & 1;
    const int g0 = blockIdx.y * 128, t0 = blockIdx.x * 128;
    const int fr = lane >> 2, kc = lane & 3;
    const int wm = (warp >> 2) * 64, wn = (warp & 3) * 32;
    const int r = tid >> 5, q = tid & 31;     // copy-chunk mapping: 8 rows x 32 chunks

    const unsigned* srcAh = g_Ah + (((long)s * KT) * 8 + r) * GP + g0 + q * 4;
    const unsigned* srcAm = g_Am + (((long)s * KT) * 8 + r) * GP + g0 + q * 4;
    const unsigned* srcBh = g_Bh + (((long)cch * KT) * 8 + r) * TP + t0 + q * 4;
    const unsigned* srcBm = g_Bm + (((long)cch * KT) * 8 + r) * TP + t0 + q * 4;
    const unsigned dstc = sb + (r * 136 + q * 4) * 4;

    auto issue = [&](int c, int buf) {
        unsigned d = dstc + buf * (STW * 4);
        CP16(d,              srcAh + (long)c * 8 * GP);
        CP16(d + AW * 4,     srcAm + (long)c * 8 * GP);
        CP16(d + 2 * AW * 4, srcBh + (long)c * 8 * TP);
        CP16(d + 3 * AW * 4, srcBm + (long)c * 8 * TP);
    };

    float acc[4][4][4];
#pragma unroll
    for (int i = 0; i < 4; i++)
#pragma unroll
        for (int j = 0; j < 4; j++)
#pragma unroll
            for (int p = 0; p < 4; p++) acc[i][j][p] = 0.f;

    issue(0, 0); CPCOMMIT();
    issue(1, 1); CPCOMMIT();

    int buf = 0;
    for (int c = 0; c < KT; c++) {
        CPWAIT1();
        __syncthreads();
        if (c + 2 < KT) issue(c + 2, (buf + 2) % 3);
        CPCOMMIT();

        const unsigned* Ah = smw + buf * STW;
        const unsigned* Am = Ah + AW;
        const unsigned* Bh = Ah + 2 * AW;
        const unsigned* Bm = Ah + 3 * AW;

        unsigned ah[4][4], am[4][4];
#pragma unroll
        for (int i = 0; i < 4; i++) {
            int mb = wm + i * 16 + fr;
            ah[i][0] = Ah[kc * 136 + mb];       ah[i][1] = Ah[kc * 136 + mb + 8];
            ah[i][2] = Ah[(kc + 4) * 136 + mb]; ah[i][3] = Ah[(kc + 4) * 136 + mb + 8];
            am[i][0] = Am[kc * 136 + mb];       am[i][1] = Am[kc * 136 + mb + 8];
            am[i][2] = Am[(kc + 4) * 136 + mb]; am[i][3] = Am[(kc + 4) * 136 + mb + 8];
        }
#pragma unroll
        for (int j = 0; j < 4; j++) {
            int nb = wn + j * 8 + fr;
            unsigned bh0 = Bh[kc * 136 + nb], bh1 = Bh[(kc + 4) * 136 + nb];
            unsigned bm0 = Bm[kc * 136 + nb], bm1 = Bm[(kc + 4) * 136 + nb];
#pragma unroll
            for (int i = 0; i < 4; i++) {
                MMA_BF16(acc[i][j], ah[i][0], ah[i][1], ah[i][2], ah[i][3], bm0, bm1);
                MMA_BF16(acc[i][j], am[i][0], am[i][1], am[i][2], am[i][3], bh0, bh1);
                MMA_BF16(acc[i][j], ah[i][0], ah[i][1], ah[i][2], ah[i][3], bh0, bh1);
            }
        }
        buf = (buf + 1) % 3;
    }

    float* C = g_V + (long)sc * FQ * NT;
    const int cc = (lane & 3) * 2;
#pragma unroll
    for (int i = 0; i < 4; i++) {
        int row = g0 + wm + i * 16 + fr;
#pragma unroll
        for (int j = 0; j < 4; j++) {
            int col = t0 + wn + j * 8 + cc;
            if (row < FQ && col + 1 < NT) {
                *(float2*)&C[(long)row * NT + col] =
                    make_float2(fmaxf(acc[i][j][0], 0.f), fmaxf(acc[i][j][1], 0.f));
            } else if (row < FQ && col < NT) {
                C[(long)row * NT + col] = fmaxf(acc[i][j][0], 0.f);
            }
            if (row + 8 < FQ && col + 1 < NT) {
                *(float2*)&C[(long)(row + 8) * NT + col] =
                    make_float2(fmaxf(acc[i][j][2], 0.f), fmaxf(acc[i][j][3], 0.f));
            } else if (row + 8 < FQ && col < NT) {
                C[(long)(row + 8) * NT + col] = fmaxf(acc[i][j][2], 0.f);
            }
        }
    }
}

__global__ __launch_bounds__(128) void wiener_kernel() {
    const int f = blockIdx.x, ck = blockIdx.y;
    const int tid = threadIdx.x;
    const float ma = fmaxf(1.0f, __int_as_float(g_cmax[ck]) * 0.1f);
    const float ima = 1.0f / ma;

    float r00[NSRC], r11[NSRC], r01r[NSRC], r01i[NSRC], vs[NSRC];
#pragma unroll
    for (int s = 0; s < NSRC; s++) { r00[s] = r11[s] = r01r[s] = r01i[s] = vs[s] = 0.f; }

    for (int t = tid; t < WINLEN; t += 128) {
        int tg = ck * WINLEN + t;
        float2 x0 = g_mix[(0 * FQ + f) * NT + tg];
        float2 x1 = g_mix[(1 * FQ + f) * NT + tg];
        float a0 = sqrtf(x0.x * x0.x + x0.y * x0.y);
        float a1 = sqrtf(x1.x * x1.x + x1.y * x1.y);
        float2 p0 = (a0 > 0.f) ? make_float2(x0.x / a0, x0.y / a0) : make_float2(1.f, 0.f);
        float2 p1 = (a1 > 0.f) ? make_float2(x1.x / a1, x1.y / a1) : make_float2(1.f, 0.f);
        float2 pc = make_float2(p0.x * p1.x + p0.y * p1.y, p0.y * p1.x - p0.x * p1.y);
#pragma unroll
        for (int s = 0; s < NSRC; s++) {
            float v0 = g_V[((s * 2 + 0) * FQ + f) * NT + tg] * ima;
            float v1 = g_V[((s * 2 + 1) * FQ + f) * NT + tg] * ima;
            r00[s] += v0 * v0;
            r11[s] += v1 * v1;
            float cr = v0 * v1;
            r01r[s] += cr * pc.x;
            r01i[s] += cr * pc.y;
            vs[s] += 0.5f * (v0 * v0 + v1 * v1);
        }
    }

    __shared__ float sacc[20][128];
#pragma unroll
    for (int s = 0; s < NSRC; s++) {
        sacc[s][tid] = r00[s];
        sacc[4 + s][tid] = r11[s];
        sacc[8 + s][tid] = r01r[s];
        sacc[12 + s][tid] = r01i[s];
        sacc[16 + s][tid] = vs[s];
    }
    __syncthreads();
    for (int off = 64; off; off >>= 1) {
        if (tid < off) {
#pragma unroll
            for (int q = 0; q < 20; q++) sacc[q][tid] += sacc[q][tid + off];
        }
        __syncthreads();
    }
    __shared__ float sR[16];
    if (tid < NSRC) {
        int s = tid;
        float inv = 1.0f / (EPSV + sacc[16 + s][0]);
        sR[s * 4 + 0] = sacc[s][0] * inv;
        sR[s * 4 + 1] = sacc[4 + s][0] * inv;
        sR[s * 4 + 2] = sacc[8 + s][0] * inv;
        sR[s * 4 + 3] = sacc[12 + s][0] * inv;
    }
    __syncthreads();

    float R00[NSRC], R11[NSRC], R01x[NSRC], R01y[NSRC];
#pragma unroll
    for (int s = 0; s < NSRC; s++) {
        R00[s] = sR[s * 4 + 0];
        R11[s] = sR[s * 4 + 1];
        R01x[s] = sR[s * 4 + 2];
        R01y[s] = sR[s * 4 + 3];
    }

    for (int t = tid; t < WINLEN; t += 128) {
        int tg = ck * WINLEN + t;
        float2 x0 = g_mix[(0 * FQ + f) * NT + tg];
        float2 x1 = g_mix[(1 * FQ + f) * NT + tg];
        float2 xs0 = make_float2(x0.x * ima, x0.y * ima);
        float2 xs1 = make_float2(x1.x * ima, x1.y * ima);

        float vloc[NSRC];
        float c00 = SQEPS, c11 = SQEPS, c01r = 0.f, c01i = 0.f;
#pragma unroll
        for (int s = 0; s < NSRC; s++) {
            float v0 = g_V[((s * 2 + 0) * FQ + f) * NT + tg] * ima;
            float v1 = g_V[((s * 2 + 1) * FQ + f) * NT + tg] * ima;
            float v = 0.5f * (v0 * v0 + v1 * v1);
            vloc[s] = v;
            c00 += v * R00[s];
            c11 += v * R11[s];
            c01r += v * R01x[s];
            c01i += v * R01y[s];
        }
        float det = c00 * c11 - (c01r * c01r + c01i * c01i);
        float idet = 1.0f / det;
        float i00 = c11 * idet, i11 = c00 * idet;
        float2 i01 = make_float2(-c01r * idet, -c01i * idet);
        float2 i10 = make_float2(-c01r * idet, c01i * idet);

#pragma unroll
        for (int s = 0; s < NSRC; s++) {
            float v = vloc[s];
            float a00 = R00[s], a11 = R11[s];
            float2 a01 = make_float2(R01x[s], R01y[s]);
            float2 a10 = make_float2(R01x[s], -R01y[s]);
            float2 G00 = make_float2(a00 * i00 + a01.x * i10.x - a01.y * i10.y,
                                     a01.x * i10.y + a01.y * i10.x);
            float2 G01 = make_float2(a00 * i01.x + a01.x * i11,
                                     a00 * i01.y + a01.y * i11);
            float2 G10 = make_float2(a10.x * i00 + a11 * i10.x,
                                     a10.y * i00 + a11 * i10.y);
            float2 G11 = make_float2(a10.x * i01.x - a10.y * i01.y + a11 * i11,
                                     a10.x * i01.y + a10.y * i01.x);
            G00.x *= v; G00.y *= v; G01.x *= v; G01.y *= v;
            G10.x *= v; G10.y *= v; G11.x *= v; G11.y *= v;

            float2 y0 = cadd(cmul(G00, xs0), cmul(G01, xs1));
            float2 y1 = cadd(cmul(G10, xs0), cmul(G11, xs1));
            g_Y[((s * 2 + 0) * FQ + f) * NT + tg] = make_float2(y0.x * ma, y0.y * ma);
            g_Y[((s * 2 + 1) * FQ + f) * NT + tg] = make_float2(y1.x * ma, y1.y * ma);
        }
    }
}

__global__ __launch_bounds__(256) void istft_kernel() {
    __shared__ float2 sh[NFFT];
    int t = blockIdx.x, s = blockIdx.y;
    for (int f = threadIdx.x; f <= NFFT / 2; f += 256) {
        float2 y0 = g_Y[((s * 2 + 0) * FQ + f) * NT + t];
        float2 y1 = g_Y[((s * 2 + 1) * FQ + f) * NT + t];
        sh[rev4(f)] = make_float2(y0.x - y1.y, y0.y + y1.x);
        if (f > 0 && f < NFFT / 2)
            sh[rev4(NFFT - f)] = make_float2(y0.x + y1.y, y1.x - y0.y);
    }
    __syncthreads();
    fft4096_r4(sh, +1);
    float* out0 = g_frames + ((s * 2 + 0) * NT + t) * NFFT;
    float* out1 = g_frames + ((s * 2 + 1) * NT + t) * NFFT;
    const float scale = 1.0f / NFFT;
    for (int n = threadIdx.x; n < NFFT; n += 256) {
        float2 z = sh[n];
        float ws = scale * g_win[n];
        out0[n] = z.x * ws;
        out1[n] = z.y * ws;
    }
}

__global__ __launch_bounds__(256) void gather_kernel(float* __restrict__ out) {
    int idx = blockIdx.x * blockDim.x + threadIdx.x;
    if (idx >= 8 * TLEN) return;
    int sc = idx / TLEN;
    int io = idx - sc * TLEN;
    int i = io + NFFT / 2;
    int tmin = (i - 3072) / 1024;
    if (tmin < 0) tmin = 0;
    int tmax = i / HOP;
    if (tmax > NT - 1) tmax = NT - 1;
    float num = 0.f, den = 0.f;
    for (int tt = tmin; tt <= tmax; ++tt) {
        int n = i - tt * HOP;
        num += g_frames[(sc * NT + tt) * NFFT + n];
        float wv = g_win[n];
        den += wv * wv;
    }
    out[idx] = num / ((den > 1e-11f) ? den : 1.0f);
}

extern "C" void kernel_launch(void* const* d_in, const int* in_sizes, int n_in,
                              void* d_out, int out_size) {
    const float* audio = (const float*)d_in[0];
    const float* Wmat = (const float*)d_in[1];
    float* out = (float*)d_out;

    cudaFuncSetAttribute(gemm_kernel, cudaFuncAttributeMaxDynamicSharedMemorySize, GSM);

    init_kernel<<<16, 256>>>();
    packA_kernel<<<dim3(KT, 17, 4), 128>>>(Wmat);
    stft_kernel<<<NT, 256>>>(audio);
    packB_kernel<<<dim3(KT, 12, 2), 128>>>();
    gemm_kernel<<<dim3(12, 17, 8), 256, GSM>>>();
    wiener_kernel<<<dim3(FQ, NCHUNK), 128>>>();
    istft_kernel<<<dim3(NT, NSRC), 256>>>();
    gather_kernel<<<(8 * TLEN + 255) / 256, 256>>>(out);
}

// round 13
// speedup vs baseline: 3.2204x; 1.1350x over previous
#include <cuda_runtime.h>
#include <cuda_bf16.h>
#include <math.h>

#define FQ     2049
#define NT     1500
#define TLEN   1535976
#define NFFT   4096
#define HOP    1024
#define NSRC   4
#define NCHUNK 5
#define WINLEN 300
#define EPSV   1e-10f
#define SQEPS  1e-5f
#define KT     129        // k tiles of 16 (K = f)
#define GP     2176       // padded g (17*128)
#define TP     1536       // padded t (12*128)
#define FP2    2064       // padded f stride

// spectral buffers in [t][f] layout
__device__ float2 g_mix[2L * TP * FP2];        // [c][t][f]
__device__ float  g_V[8L * TP * FP2];          // [sc][t][f]
__device__ float2 g_Y[8L * TP * FP2];          // [sc][t][f]
__device__ float  g_frames[8 * NT * NFFT];
__device__ float2 g_tw[3072];
__device__ float  g_win[NFFT];
__device__ int    g_cmax[NCHUNK];
__device__ float  g_magT[2L * TP * FP2];                    // [c][t][f]
__device__ __align__(16) unsigned g_Ah[4L * KT * 8 * GP];   // W packed [s][kt][p][g]
__device__ __align__(16) unsigned g_Am[4L * KT * 8 * GP];
__device__ __align__(16) unsigned g_Bh[2L * KT * 8 * TP];   // mag packed [c][kt][p][t]
__device__ __align__(16) unsigned g_Bm[2L * KT * 8 * TP];

__device__ __forceinline__ float2 cmul(float2 a, float2 b) {
    return make_float2(a.x * b.x - a.y * b.y, a.x * b.y + a.y * b.x);
}
__device__ __forceinline__ float2 cadd(float2 a, float2 b) {
    return make_float2(a.x + b.x, a.y + b.y);
}
__device__ __forceinline__ int rev4(int n) {
    unsigned r = __brev((unsigned)n) >> 20;
    return (int)(((r & 0x555u) << 1) | ((r >> 1) & 0x555u));
}
__device__ __forceinline__ unsigned pack2(float v0, float v1, bool mid) {
    __nv_bfloat16 h0 = __float2bfloat16(v0), h1 = __float2bfloat16(v1);
    if (mid) {
        h0 = __float2bfloat16(v0 - __bfloat162float(h0));
        h1 = __float2bfloat16(v1 - __bfloat162float(h1));
    }
    return ((unsigned)__bfloat16_as_ushort(h1) << 16) | __bfloat16_as_ushort(h0);
}

__device__ void fft4096_r4(float2* sh, int sign) {
#pragma unroll
    for (int st = 0; st < 6; st++) {
        const int q = 1 << (2 * st);
        const int stepT = 1024 >> (2 * st);
        for (int j = threadIdx.x; j < 1024; j += 256) {
            int k = j & (q - 1);
            int base = ((j - k) << 2) + k;
            float2 w1 = g_tw[k * stepT];
            float2 w2 = g_tw[2 * k * stepT];
            float2 w3 = g_tw[3 * k * stepT];
            if (sign > 0) { w1.y = -w1.y; w2.y = -w2.y; w3.y = -w3.y; }
            float2 a0 = sh[base];
            float2 a1 = cmul(sh[base + q], w1);
            float2 a2 = cmul(sh[base + 2 * q], w2);
            float2 a3 = cmul(sh[base + 3 * q], w3);
            float2 b0 = make_float2(a0.x + a2.x, a0.y + a2.y);
            float2 b1 = make_float2(a0.x - a2.x, a0.y - a2.y);
            float2 b2 = make_float2(a1.x + a3.x, a1.y + a3.y);
            float2 b3 = make_float2(a1.x - a3.x, a1.y - a3.y);
            float2 rot = (sign < 0) ? make_float2(b3.y, -b3.x)
                                    : make_float2(-b3.y, b3.x);
            sh[base]         = make_float2(b0.x + b2.x, b0.y + b2.y);
            sh[base + q]     = make_float2(b1.x + rot.x, b1.y + rot.y);
            sh[base + 2 * q] = make_float2(b0.x - b2.x, b0.y - b2.y);
            sh[base + 3 * q] = make_float2(b1.x - rot.x, b1.y - rot.y);
        }
        __syncthreads();
    }
}

__global__ void init_kernel() {
    int i = blockIdx.x * blockDim.x + threadIdx.x;
    if (i < 3072) {
        float s, c;
        sincospif(i * (1.0f / 2048.0f), &s, &c);
        g_tw[i] = make_float2(c, -s);
    }
    if (i < NFFT) g_win[i] = 0.5f * (1.0f - cospif(i * (1.0f / 2048.0f)));
    if (i < NCHUNK) g_cmax[i] = 0;
}

// W[s][g][k] -> fragment-ready tiles [s][kt][p][g]
__global__ void packA_kernel(const float* __restrict__ W) {
    int kt = blockIdx.x, s = blockIdx.z;
    int m = blockIdx.y * 128 + threadIdx.x;
    long base = (((long)s * KT + kt) * 8) * GP + m;
    if (m >= FQ) {
#pragma unroll
        for (int p = 0; p < 8; p++) { g_Ah[base + p * GP] = 0; g_Am[base + p * GP] = 0; }
        return;
    }
    const float* Wr = W + (long)s * FQ * FQ + (long)m * FQ;
#pragma unroll
    for (int p = 0; p < 8; p++) {
        int k = kt * 16 + 2 * p;
        float v0 = (k < FQ) ? __ldg(&Wr[k]) : 0.f;
        float v1 = (k + 1 < FQ) ? __ldg(&Wr[k + 1]) : 0.f;
        g_Ah[base + p * GP] = pack2(v0, v1, false);
        g_Am[base + p * GP] = pack2(v0, v1, true);
    }
}

// magT[c][t][f] -> fragment-ready tiles [c][kt][p][t]
__global__ void packB_kernel() {
    int kt = blockIdx.x, c = blockIdx.z;
    int t = blockIdx.y * 128 + threadIdx.x;
    const float* Mr = g_magT + ((long)c * TP + t) * FP2 + kt * 16;
    long base = (((long)c * KT + kt) * 8) * TP + t;
#pragma unroll
    for (int p = 0; p < 8; p++) {
        float v0 = Mr[2 * p], v1 = Mr[2 * p + 1];
        g_Bh[base + p * TP] = pack2(v0, v1, false);
        g_Bm[base + p * TP] = pack2(v0, v1, true);
    }
}

__global__ __launch_bounds__(256) void stft_kernel(const float* __restrict__ audio) {
    __shared__ float2 sh[NFFT];
    __shared__ float smax[256];
    int t = blockIdx.x;
    for (int n = threadIdx.x; n < NFFT; n += 256) {
        int j = t * HOP + n - (NFFT / 2);
        if (j < 0) j = -j;
        if (j >= TLEN) j = 2 * (TLEN - 1) - j;
        float w = g_win[n];
        sh[rev4(n)] = make_float2(audio[j] * w, audio[TLEN + j] * w);
    }
    __syncthreads();
    fft4096_r4(sh, -1);
    float lmax = 0.f;
    for (int f = threadIdx.x; f <= NFFT / 2; f += 256) {
        float2 A = sh[f];
        float2 Zn = sh[(NFFT - f) & (NFFT - 1)];
        float2 x0 = make_float2(0.5f * (A.x + Zn.x), 0.5f * (A.y - Zn.y));
        float2 x1 = make_float2(0.5f * (A.y + Zn.y), 0.5f * (Zn.x - A.x));
        g_mix[(0L * TP + t) * FP2 + f] = x0;
        g_mix[(1L * TP + t) * FP2 + f] = x1;
        float m0 = sqrtf(x0.x * x0.x + x0.y * x0.y);
        float m1 = sqrtf(x1.x * x1.x + x1.y * x1.y);
        g_magT[(0L * TP + t) * FP2 + f] = m0;
        g_magT[(1L * TP + t) * FP2 + f] = m1;
        lmax = fmaxf(lmax, fmaxf(m0, m1));
    }
    smax[threadIdx.x] = lmax;
    __syncthreads();
    for (int off = 128; off; off >>= 1) {
        if (threadIdx.x < off) smax[threadIdx.x] = fmaxf(smax[threadIdx.x], smax[threadIdx.x + off]);
        __syncthreads();
    }
    if (threadIdx.x == 0) atomicMax(&g_cmax[t / WINLEN], __float_as_int(smax[0]));
}

// ---------------- GEMM (transposed): V^T[t][g] = mag^T @ W^T, bf16x3, cp.async ----------------
#define AW   1088
#define STW  4352
#define GSM  52224

#define MMA_BF16(d, a0, a1, a2, a3, b0, b1)                                      \
    asm volatile("mma.sync.aligned.m16n8k16.row.col.f32.bf16.bf16.f32 "          \
                 "{%0,%1,%2,%3}, {%4,%5,%6,%7}, {%8,%9}, {%0,%1,%2,%3};\n"       \
                 : "+f"(d[0]), "+f"(d[1]), "+f"(d[2]), "+f"(d[3])                 \
                 : "r"(a0), "r"(a1), "r"(a2), "r"(a3), "r"(b0), "r"(b1))
#define CP16(d, s) asm volatile("cp.async.cg.shared.global [%0], [%1], 16;" :: "r"(d), "l"(s) : "memory")
#define CPCOMMIT() asm volatile("cp.async.commit_group;" ::: "memory")
#define CPWAIT1()  asm volatile("cp.async.wait_group 1;" ::: "memory")

__global__ __launch_bounds__(256, 2) void gemm_kernel() {
    extern __shared__ __align__(16) unsigned smw[];
    unsigned sb;
    asm("{ .reg .u64 t; cvta.to.shared.u64 t, %1; cvt.u32.u64 %0, t; }" : "=r"(sb) : "l"(smw));
    const int tid = threadIdx.x, warp = tid >> 5, lane = tid & 31;
    const int sc = blockIdx.z, s = sc >> 1, cch = sc & 1;
    const int t0 = blockIdx.x * 128, g0 = blockIdx.y * 128;   // M = t, N = g
    const int fr = lane >> 2, kc = lane & 3;
    const int wm = (warp >> 2) * 64, wn = (warp & 3) * 32;
    const int r = tid >> 5, q = tid & 31;

    // A operand = mag (m = t), B operand = W (n = g)
    const unsigned* srcAh = g_Bh + (((long)cch * KT) * 8 + r) * TP + t0 + q * 4;
    const unsigned* srcAm = g_Bm + (((long)cch * KT) * 8 + r) * TP + t0 + q * 4;
    const unsigned* srcBh = g_Ah + (((long)s * KT) * 8 + r) * GP + g0 + q * 4;
    const unsigned* srcBm = g_Am + (((long)s * KT) * 8 + r) * GP + g0 + q * 4;
    const unsigned dstc = sb + (r * 136 + q * 4) * 4;

    auto issue = [&](int c, int buf) {
        unsigned d = dstc + buf * (STW * 4);
        CP16(d,              srcAh + (long)c * 8 * TP);
        CP16(d + AW * 4,     srcAm + (long)c * 8 * TP);
        CP16(d + 2 * AW * 4, srcBh + (long)c * 8 * GP);
        CP16(d + 3 * AW * 4, srcBm + (long)c * 8 * GP);
    };

    float acc[4][4][4];
#pragma unroll
    for (int i = 0; i < 4; i++)
#pragma unroll
        for (int j = 0; j < 4; j++)
#pragma unroll
            for (int p = 0; p < 4; p++) acc[i][j][p] = 0.f;

    issue(0, 0); CPCOMMIT();
    issue(1, 1); CPCOMMIT();

    int buf = 0;
    for (int c = 0; c < KT; c++) {
        CPWAIT1();
        __syncthreads();
        if (c + 2 < KT) issue(c + 2, (buf + 2) % 3);
        CPCOMMIT();

        const unsigned* Ah = smw + buf * STW;
        const unsigned* Am = Ah + AW;
        const unsigned* Bh = Ah + 2 * AW;
        const unsigned* Bm = Ah + 3 * AW;

        unsigned ah[4][4], am[4][4];
#pragma unroll
        for (int i = 0; i < 4; i++) {
            int mb = wm + i * 16 + fr;
            ah[i][0] = Ah[kc * 136 + mb];       ah[i][1] = Ah[kc * 136 + mb + 8];
            ah[i][2] = Ah[(kc + 4) * 136 + mb]; ah[i][3] = Ah[(kc + 4) * 136 + mb + 8];
            am[i][0] = Am[kc * 136 + mb];       am[i][1] = Am[kc * 136 + mb + 8];
            am[i][2] = Am[(kc + 4) * 136 + mb]; am[i][3] = Am[(kc + 4) * 136 + mb + 8];
        }
#pragma unroll
        for (int j = 0; j < 4; j++) {
            int nb = wn + j * 8 + fr;
            unsigned bh0 = Bh[kc * 136 + nb], bh1 = Bh[(kc + 4) * 136 + nb];
            unsigned bm0 = Bm[kc * 136 + nb], bm1 = Bm[(kc + 4) * 136 + nb];
#pragma unroll
            for (int i = 0; i < 4; i++) {
                MMA_BF16(acc[i][j], ah[i][0], ah[i][1], ah[i][2], ah[i][3], bm0, bm1);
                MMA_BF16(acc[i][j], am[i][0], am[i][1], am[i][2], am[i][3], bh0, bh1);
                MMA_BF16(acc[i][j], ah[i][0], ah[i][1], ah[i][2], ah[i][3], bh0, bh1);
            }
        }
        buf = (buf + 1) % 3;
    }

    float* C = g_V + (long)sc * TP * FP2;
    const int cc = (lane & 3) * 2;
#pragma unroll
    for (int i = 0; i < 4; i++) {
        int row = t0 + wm + i * 16 + fr;          // t
#pragma unroll
        for (int j = 0; j < 4; j++) {
            int col = g0 + wn + j * 8 + cc;       // g
            if (row < NT && col + 1 < FQ) {
                *(float2*)&C[(long)row * FP2 + col] =
                    make_float2(fmaxf(acc[i][j][0], 0.f), fmaxf(acc[i][j][1], 0.f));
            } else if (row < NT && col < FQ) {
                C[(long)row * FP2 + col] = fmaxf(acc[i][j][0], 0.f);
            }
            if (row + 8 < NT && col + 1 < FQ) {
                *(float2*)&C[(long)(row + 8) * FP2 + col] =
                    make_float2(fmaxf(acc[i][j][2], 0.f), fmaxf(acc[i][j][3], 0.f));
            } else if (row + 8 < NT && col < FQ) {
                C[(long)(row + 8) * FP2 + col] = fmaxf(acc[i][j][2], 0.f);
            }
        }
    }
}

// ---------------- Wiener EM: block = 32-f tile x chunk, coalesced over f ----------------
__global__ __launch_bounds__(256) void wiener_kernel() {
    const int ck = blockIdx.y;
    const int tid = threadIdx.x;
    const int fx = tid & 31, ty = tid >> 5;     // 8 t-lanes
    const int f = blockIdx.x * 32 + fx;
    const bool fv = f < FQ;
    const float ma = fmaxf(1.0f, __int_as_float(g_cmax[ck]) * 0.1f);
    const float ima = 1.0f / ma;

    float r00[NSRC], r11[NSRC], r01r[NSRC], r01i[NSRC], vs[NSRC];
#pragma unroll
    for (int s = 0; s < NSRC; s++) { r00[s] = r11[s] = r01r[s] = r01i[s] = vs[s] = 0.f; }

    for (int t = ty; t < WINLEN; t += 8) {
        long tg = (long)(ck * WINLEN + t);
        float2 x0 = fv ? g_mix[(0L * TP + tg) * FP2 + f] : make_float2(0.f, 0.f);
        float2 x1 = fv ? g_mix[(1L * TP + tg) * FP2 + f] : make_float2(0.f, 0.f);
        float a0 = sqrtf(x0.x * x0.x + x0.y * x0.y);
        float a1 = sqrtf(x1.x * x1.x + x1.y * x1.y);
        float2 p0 = (a0 > 0.f) ? make_float2(x0.x / a0, x0.y / a0) : make_float2(1.f, 0.f);
        float2 p1 = (a1 > 0.f) ? make_float2(x1.x / a1, x1.y / a1) : make_float2(1.f, 0.f);
        float2 pc = make_float2(p0.x * p1.x + p0.y * p1.y, p0.y * p1.x - p0.x * p1.y);
#pragma unroll
        for (int s = 0; s < NSRC; s++) {
            float v0 = fv ? g_V[((2L * s + 0) * TP + tg) * FP2 + f] * ima : 0.f;
            float v1 = fv ? g_V[((2L * s + 1) * TP + tg) * FP2 + f] * ima : 0.f;
            r00[s] += v0 * v0;
            r11[s] += v1 * v1;
            float cr = v0 * v1;
            r01r[s] += cr * pc.x;
            r01i[s] += cr * pc.y;
            vs[s] += 0.5f * (v0 * v0 + v1 * v1);
        }
    }

    __shared__ float sred[20][256];
#pragma unroll
    for (int s = 0; s < NSRC; s++) {
        sred[s][tid] = r00[s];
        sred[4 + s][tid] = r11[s];
        sred[8 + s][tid] = r01r[s];
        sred[12 + s][tid] = r01i[s];
        sred[16 + s][tid] = vs[s];
    }
    __syncthreads();
    __shared__ float sR[16][33];
    if (tid < 128) {
        int s = tid >> 5, fxx = tid & 31;
        float t00 = 0, t11 = 0, t0r = 0, t0i = 0, tvs = 0;
#pragma unroll
        for (int y = 0; y < 8; y++) {
            t00 += sred[s][y * 32 + fxx];
            t11 += sred[4 + s][y * 32 + fxx];
            t0r += sred[8 + s][y * 32 + fxx];
            t0i += sred[12 + s][y * 32 + fxx];
            tvs += sred[16 + s][y * 32 + fxx];
        }
        float inv = 1.0f / (EPSV + tvs);
        sR[s * 4 + 0][fxx] = t00 * inv;
        sR[s * 4 + 1][fxx] = t11 * inv;
        sR[s * 4 + 2][fxx] = t0r * inv;
        sR[s * 4 + 3][fxx] = t0i * inv;
    }
    __syncthreads();

    float R00[NSRC], R11[NSRC], R01x[NSRC], R01y[NSRC];
#pragma unroll
    for (int s = 0; s < NSRC; s++) {
        R00[s] = sR[s * 4 + 0][fx];
        R11[s] = sR[s * 4 + 1][fx];
        R01x[s] = sR[s * 4 + 2][fx];
        R01y[s] = sR[s * 4 + 3][fx];
    }

    if (!fv) return;
    for (int t = ty; t < WINLEN; t += 8) {
        long tg = (long)(ck * WINLEN + t);
        float2 x0 = g_mix[(0L * TP + tg) * FP2 + f];
        float2 x1 = g_mix[(1L * TP + tg) * FP2 + f];
        float2 xs0 = make_float2(x0.x * ima, x0.y * ima);
        float2 xs1 = make_float2(x1.x * ima, x1.y * ima);

        float vloc[NSRC];
        float c00 = SQEPS, c11 = SQEPS, c01r = 0.f, c01i = 0.f;
#pragma unroll
        for (int s = 0; s < NSRC; s++) {
            float v0 = g_V[((2L * s + 0) * TP + tg) * FP2 + f] * ima;
            float v1 = g_V[((2L * s + 1) * TP + tg) * FP2 + f] * ima;
            float v = 0.5f * (v0 * v0 + v1 * v1);
            vloc[s] = v;
            c00 += v * R00[s];
            c11 += v * R11[s];
            c01r += v * R01x[s];
            c01i += v * R01y[s];
        }
        float det = c00 * c11 - (c01r * c01r + c01i * c01i);
        float idet = 1.0f / det;
        float i00 = c11 * idet, i11 = c00 * idet;
        float2 i01 = make_float2(-c01r * idet, -c01i * idet);
        float2 i10 = make_float2(-c01r * idet, c01i * idet);

#pragma unroll
        for (int s = 0; s < NSRC; s++) {
            float v = vloc[s];
            float a00 = R00[s], a11 = R11[s];
            float2 a01 = make_float2(R01x[s], R01y[s]);
            float2 a10 = make_float2(R01x[s], -R01y[s]);
            float2 G00 = make_float2(a00 * i00 + a01.x * i10.x - a01.y * i10.y,
                                     a01.x * i10.y + a01.y * i10.x);
            float2 G01 = make_float2(a00 * i01.x + a01.x * i11,
                                     a00 * i01.y + a01.y * i11);
            float2 G10 = make_float2(a10.x * i00 + a11 * i10.x,
                                     a10.y * i00 + a11 * i10.y);
            float2 G11 = make_float2(a10.x * i01.x - a10.y * i01.y + a11 * i11,
                                     a10.x * i01.y + a10.y * i01.x);
            G00.x *= v; G00.y *= v; G01.x *= v; G01.y *= v;
            G10.x *= v; G10.y *= v; G11.x *= v; G11.y *= v;

            float2 y0 = cadd(cmul(G00, xs0), cmul(G01, xs1));
            float2 y1 = cadd(cmul(G10, xs0), cmul(G11, xs1));
            g_Y[((2L * s + 0) * TP + tg) * FP2 + f] = make_float2(y0.x * ma, y0.y * ma);
            g_Y[((2L * s + 1) * TP + tg) * FP2 + f] = make_float2(y1.x * ma, y1.y * ma);
        }
    }
}

__global__ __launch_bounds__(256) void istft_kernel() {
    __shared__ float2 sh[NFFT];
    int t = blockIdx.x, s = blockIdx.y;
    for (int f = threadIdx.x; f <= NFFT / 2; f += 256) {
        float2 y0 = g_Y[((2L * s + 0) * TP + t) * FP2 + f];
        float2 y1 = g_Y[((2L * s + 1) * TP + t) * FP2 + f];
        sh[rev4(f)] = make_float2(y0.x - y1.y, y0.y + y1.x);
        if (f > 0 && f < NFFT / 2)
            sh[rev4(NFFT - f)] = make_float2(y0.x + y1.y, y1.x - y0.y);
    }
    __syncthreads();
    fft4096_r4(sh, +1);
    float* out0 = g_frames + ((s * 2 + 0) * NT + t) * NFFT;
    float* out1 = g_frames + ((s * 2 + 1) * NT + t) * NFFT;
    const float scale = 1.0f / NFFT;
    for (int n = threadIdx.x; n < NFFT; n += 256) {
        float2 z = sh[n];
        float ws = scale * g_win[n];
        out0[n] = z.x * ws;
        out1[n] = z.y * ws;
    }
}

__global__ __launch_bounds__(256) void gather_kernel(float* __restrict__ out) {
    int idx = blockIdx.x * blockDim.x + threadIdx.x;
    if (idx >= 8 * TLEN) return;
    int sc = idx / TLEN;
    int io = idx - sc * TLEN;
    int i = io + NFFT / 2;
    int tmin = (i - 3072) / 1024;
    if (tmin < 0) tmin = 0;
    int tmax = i / HOP;
    if (tmax > NT - 1) tmax = NT - 1;
    float num = 0.f, den = 0.f;
    for (int tt = tmin; tt <= tmax; ++tt) {
        int n = i - tt * HOP;
        num += g_frames[(sc * NT + tt) * NFFT + n];
        float wv = g_win[n];
        den += wv * wv;
    }
    out[idx] = num / ((den > 1e-11f) ? den : 1.0f);
}

extern "C" void kernel_launch(void* const* d_in, const int* in_sizes, int n_in,
                              void* d_out, int out_size) {
    const float* audio = (const float*)d_in[0];
    const float* Wmat = (const float*)d_in[1];
    float* out = (float*)d_out;

    cudaFuncSetAttribute(gemm_kernel, cudaFuncAttributeMaxDynamicSharedMemorySize, GSM);

    init_kernel<<<16, 256>>>();
    packA_kernel<<<dim3(KT, 17, 4), 128>>>(Wmat);
    stft_kernel<<<NT, 256>>>(audio);
    packB_kernel<<<dim3(KT, 12, 2), 128>>>();
    gemm_kernel<<<dim3(12, 17, 8), 256, GSM>>>();
    wiener_kernel<<<dim3(65, NCHUNK), 256>>>();
    istft_kernel<<<dim3(NT, NSRC), 256>>>();
    gather_kernel<<<(8 * TLEN + 255) / 256, 256>>>(out);
}